// round 1
// baseline (speedup 1.0000x reference)
#include <cuda_runtime.h>
#include <cstdint>

#define NPTS 50000
#define CH_IN 512
#define PP 128
#define KNB 27
#define RBLK 128
#define EPSV 1e-5f

// ---------------- scratch (device globals; no allocation allowed) ----------
__device__ float g_bufA[(size_t)NPTS * PP];   // ping
__device__ float g_bufB[(size_t)NPTS * PP];   // pong
__device__ float g_valid[NPTS];
__device__ float g_ratio[NPTS];
__device__ float g_m2[NPTS];
__device__ float g_part[(size_t)RBLK * CH_IN * 2];
__device__ float g_mu[CH_IN];
__device__ float g_rs[CH_IN];

// ---------------- small kernels -------------------------------------------
__global__ void valid_kernel(const float* __restrict__ mask) {
    int n = blockIdx.x * blockDim.x + threadIdx.x;
    if (n < NPTS) g_valid[n] = mask[n] > 0.f ? 1.f : 0.f;
}

__global__ void ratio_kernel(const float* __restrict__ mask,
                             const int* __restrict__ nbr,
                             float* __restrict__ mout) {
    int n = blockIdx.x * blockDim.x + threadIdx.x;
    if (n >= NPTS) return;
    float s = 0.f;
#pragma unroll
    for (int k = 0; k < KNB; k++) s += g_valid[nbr[(size_t)n * KNB + k]];
    float has = s > 0.f ? 1.f : 0.f;
    g_ratio[n] = has * (27.f / fmaxf(s, 1.f));
    g_m2[n]    = has;
    mout[n]    = fminf(has + mask[n], 1.f);   // clip(m2 + mask, 0, 1)
}

// two-stage deterministic per-channel mean/var
__global__ void stats_partial(const float* __restrict__ X, int C, int M) {
    int c = threadIdx.x;          // blockDim.x == C
    int per = (M + gridDim.x - 1) / gridDim.x;
    int r0 = blockIdx.x * per;
    int r1 = min(r0 + per, M);
    float s = 0.f, q = 0.f;
    for (int r = r0; r < r1; r++) {
        float v = X[(size_t)r * C + c];
        s += v; q += v * v;
    }
    g_part[((size_t)blockIdx.x * C + c) * 2 + 0] = s;
    g_part[((size_t)blockIdx.x * C + c) * 2 + 1] = q;
}

__global__ void stats_final(int C, int M) {
    int c = threadIdx.x;          // 1 block, blockDim == C
    float s = 0.f, q = 0.f;
    for (int r = 0; r < RBLK; r++) {
        s += g_part[((size_t)r * C + c) * 2 + 0];
        q += g_part[((size_t)r * C + c) * 2 + 1];
    }
    float mu  = s / (float)M;
    float var = q / (float)M - mu * mu;
    g_mu[c] = mu;
    g_rs[c] = rsqrtf(fmaxf(var, 0.f) + EPSV);
}

__global__ void ew_norm_lrelu_mask(const float* __restrict__ in, float* __restrict__ outp) {
    int idx = blockIdx.x * blockDim.x + threadIdx.x;
    if (idx >= NPTS * PP) return;
    int c = idx & (PP - 1);
    int n = idx >> 7;
    float v = (in[idx] - g_mu[c]) * g_rs[c];
    v = v >= 0.f ? v : 0.1f * v;
    outp[idx] = v * g_valid[n];
}

__global__ void ew_norm_lrelu(const float* __restrict__ in, float* __restrict__ outp) {
    int idx = blockIdx.x * blockDim.x + threadIdx.x;
    if (idx >= NPTS * PP) return;
    int c = idx & (PP - 1);
    float v = (in[idx] - g_mu[c]) * g_rs[c];
    outp[idx] = v >= 0.f ? v : 0.1f * v;
}

__global__ void ew_final(const float* __restrict__ x, float* __restrict__ outp) {
    size_t idx = (size_t)blockIdx.x * blockDim.x + threadIdx.x;
    if (idx >= (size_t)NPTS * CH_IN) return;
    int c = (int)(idx & (CH_IN - 1));
    float v = (outp[idx] - g_mu[c]) * g_rs[c] + x[idx];
    outp[idx] = v >= 0.f ? v : 0.1f * v;
}

// ---------------- dense SGEMM: C[M,*] = A[M,Kd] @ B[Kd,*], epilogue *rowscale
__global__ __launch_bounds__(256, 2) void sgemm_dense(
    const float* __restrict__ A, int lda,
    const float* __restrict__ B, int ldb,
    float* __restrict__ C, int ldc,
    int M, int Kd,
    const float* __restrict__ rowscale) {
    __shared__ float As[16][132];
    __shared__ float Bs[16][128];
    const int tid  = threadIdx.x;
    const int row0 = blockIdx.y * 128;
    const int col0 = blockIdx.x * 128;
    const int tr = (tid >> 4) << 3;
    const int tc = (tid & 15) << 3;
    float acc[8][8];
#pragma unroll
    for (int i = 0; i < 8; i++)
#pragma unroll
        for (int j = 0; j < 8; j++) acc[i][j] = 0.f;

    for (int k0 = 0; k0 < Kd; k0 += 16) {
#pragma unroll
        for (int p = 0; p < 2; p++) {
            int r  = (tid >> 2) + p * 64;
            int cc = (tid & 3) << 2;
            int gr = row0 + r;
            float4 v = make_float4(0.f, 0.f, 0.f, 0.f);
            if (gr < M) v = *(const float4*)(A + (size_t)gr * lda + k0 + cc);
            As[cc + 0][r] = v.x; As[cc + 1][r] = v.y;
            As[cc + 2][r] = v.z; As[cc + 3][r] = v.w;
        }
#pragma unroll
        for (int p = 0; p < 2; p++) {
            int r  = (tid >> 5) + p * 8;
            int cc = (tid & 31) << 2;
            *(float4*)&Bs[r][cc] = *(const float4*)(B + (size_t)(k0 + r) * ldb + col0 + cc);
        }
        __syncthreads();
#pragma unroll
        for (int kk = 0; kk < 16; kk++) {
            float a[8], b[8];
            *(float4*)&a[0] = *(const float4*)&As[kk][tr];
            *(float4*)&a[4] = *(const float4*)&As[kk][tr + 4];
            *(float4*)&b[0] = *(const float4*)&Bs[kk][tc];
            *(float4*)&b[4] = *(const float4*)&Bs[kk][tc + 4];
#pragma unroll
            for (int i = 0; i < 8; i++)
#pragma unroll
                for (int j = 0; j < 8; j++)
                    acc[i][j] = fmaf(a[i], b[j], acc[i][j]);
        }
        __syncthreads();
    }
#pragma unroll
    for (int i = 0; i < 8; i++) {
        int gr = row0 + tr + i;
        if (gr < M) {
            float s = rowscale[gr];
            float* cp = C + (size_t)gr * ldc + col0 + tc;
            float4 v0 = make_float4(acc[i][0]*s, acc[i][1]*s, acc[i][2]*s, acc[i][3]*s);
            float4 v1 = make_float4(acc[i][4]*s, acc[i][5]*s, acc[i][6]*s, acc[i][7]*s);
            *(float4*)cp       = v0;
            *(float4*)(cp + 4) = v1;
        }
    }
}

// ---------------- gathered SGEMM: C[n,:] = sum_k H[nbr[n,k],:] @ W2[k], *ratio
__global__ __launch_bounds__(256, 2) void sgemm_gather(
    const float* __restrict__ H,      // [NPTS, 128] masked h1
    const int*   __restrict__ nbr,    // [NPTS, 27]
    const float* __restrict__ B,      // W2 as [3456, 128]
    float* __restrict__ C,            // [NPTS, 128]
    int M,
    const float* __restrict__ rowscale) {
    __shared__ float As[16][132];
    __shared__ float Bs[16][128];
    __shared__ int   snbr[128 * KNB];
    const int tid  = threadIdx.x;
    const int row0 = blockIdx.y * 128;
    const int tr = (tid >> 4) << 3;
    const int tc = (tid & 15) << 3;

    for (int i = tid; i < 128 * KNB; i += 256) {
        int r  = i / KNB;
        int gr = row0 + r;
        snbr[i] = (gr < M) ? nbr[(size_t)gr * KNB + (i % KNB)] : 0;
    }
    __syncthreads();

    float acc[8][8];
#pragma unroll
    for (int i = 0; i < 8; i++)
#pragma unroll
        for (int j = 0; j < 8; j++) acc[i][j] = 0.f;

    const int Kd = KNB * PP;  // 3456
    for (int k0 = 0; k0 < Kd; k0 += 16) {
        const int k  = k0 >> 7;
        const int c0 = k0 & 127;
#pragma unroll
        for (int p = 0; p < 2; p++) {
            int r   = (tid >> 2) + p * 64;
            int cc  = (tid & 3) << 2;
            int idx = snbr[r * KNB + k];
            float4 v = *(const float4*)(H + (size_t)idx * PP + c0 + cc);
            As[cc + 0][r] = v.x; As[cc + 1][r] = v.y;
            As[cc + 2][r] = v.z; As[cc + 3][r] = v.w;
        }
#pragma unroll
        for (int p = 0; p < 2; p++) {
            int r  = (tid >> 5) + p * 8;
            int cc = (tid & 31) << 2;
            *(float4*)&Bs[r][cc] = *(const float4*)(B + (size_t)(k0 + r) * PP + cc);
        }
        __syncthreads();
#pragma unroll
        for (int kk = 0; kk < 16; kk++) {
            float a[8], b[8];
            *(float4*)&a[0] = *(const float4*)&As[kk][tr];
            *(float4*)&a[4] = *(const float4*)&As[kk][tr + 4];
            *(float4*)&b[0] = *(const float4*)&Bs[kk][tc];
            *(float4*)&b[4] = *(const float4*)&Bs[kk][tc + 4];
#pragma unroll
            for (int i = 0; i < 8; i++)
#pragma unroll
                for (int j = 0; j < 8; j++)
                    acc[i][j] = fmaf(a[i], b[j], acc[i][j]);
        }
        __syncthreads();
    }
#pragma unroll
    for (int i = 0; i < 8; i++) {
        int gr = row0 + tr + i;
        if (gr < M) {
            float s = rowscale[gr];
            float* cp = C + (size_t)gr * PP + tc;
            float4 v0 = make_float4(acc[i][0]*s, acc[i][1]*s, acc[i][2]*s, acc[i][3]*s);
            float4 v1 = make_float4(acc[i][4]*s, acc[i][5]*s, acc[i][6]*s, acc[i][7]*s);
            *(float4*)cp       = v0;
            *(float4*)(cp + 4) = v1;
        }
    }
}

// ---------------- launch ---------------------------------------------------
extern "C" void kernel_launch(void* const* d_in, const int* in_sizes, int n_in,
                              void* d_out, int out_size) {
    const float* x    = (const float*)d_in[0];
    const float* mask = (const float*)d_in[1];
    const int*   nbr  = (const int*)d_in[2];
    const float* W1   = (const float*)d_in[3];
    const float* W2   = (const float*)d_in[4];
    const float* W3   = (const float*)d_in[5];
    float* out  = (float*)d_out;
    float* mout = out + (size_t)NPTS * CH_IN;

    float *pA, *pB, *pValid, *pRatio, *pM2;
    cudaGetSymbolAddress((void**)&pA,     g_bufA);
    cudaGetSymbolAddress((void**)&pB,     g_bufB);
    cudaGetSymbolAddress((void**)&pValid, g_valid);
    cudaGetSymbolAddress((void**)&pRatio, g_ratio);
    cudaGetSymbolAddress((void**)&pM2,    g_m2);

    const int nb = (NPTS + 255) / 256;
    valid_kernel<<<nb, 256>>>(mask);
    ratio_kernel<<<nb, 256>>>(mask, nbr, mout);

    dim3 gy1(1, (NPTS + 127) / 128);
    // conv1: t1 = (x @ W1) * valid
    sgemm_dense<<<gy1, 256>>>(x, CH_IN, W1, PP, pA, PP, NPTS, CH_IN, pValid);
    stats_partial<<<RBLK, PP>>>(pA, PP, NPTS);
    stats_final<<<1, PP>>>(PP, NPTS);
    // h1m = lrelu(inorm(t1)) * valid
    ew_norm_lrelu_mask<<<(NPTS * PP + 255) / 256, 256>>>(pA, pB);

    // conv2 (gathered): t2 = einsum(h1m[nbr], W2) * ratio
    sgemm_gather<<<gy1, 256>>>(pB, nbr, W2, pA, NPTS, pRatio);
    stats_partial<<<RBLK, PP>>>(pA, PP, NPTS);
    stats_final<<<1, PP>>>(PP, NPTS);
    // h2 = lrelu(inorm(t2))
    ew_norm_lrelu<<<(NPTS * PP + 255) / 256, 256>>>(pA, pB);

    // conv3: out = (h2 @ W3) * m2
    dim3 gy3(CH_IN / 128, (NPTS + 127) / 128);
    sgemm_dense<<<gy3, 256>>>(pB, PP, W3, CH_IN, out, CH_IN, NPTS, PP, pM2);
    stats_partial<<<RBLK, CH_IN>>>(out, CH_IN, NPTS);
    stats_final<<<1, CH_IN>>>(CH_IN, NPTS);
    // out = lrelu(inorm(out) + x)
    ew_final<<<(int)(((size_t)NPTS * CH_IN + 255) / 256), 256>>>(x, out);
}

// round 4
// speedup vs baseline: 2.4393x; 2.4393x over previous
#include <cuda_runtime.h>
#include <cuda_fp16.h>
#include <cstdint>

#define NPTS 50000
#define CH_IN 512
#define PP 128
#define KNB 27
#define RBLK 512
#define EPSV 1e-5f

typedef __half half_t;

// ---------------- scratch (device globals) ----------------------------------
__device__ float  g_bufA[(size_t)NPTS * PP];
__device__ half_t g_xh[(size_t)NPTS * CH_IN];
__device__ half_t g_xl[(size_t)NPTS * CH_IN];
__device__ half_t g_hh[(size_t)NPTS * PP];
__device__ half_t g_hl[(size_t)NPTS * PP];
__device__ half_t g_w1h[PP * CH_IN],      g_w1l[PP * CH_IN];        // [128 n][512 k]
__device__ half_t g_w2h[PP * KNB * PP],   g_w2l[PP * KNB * PP];     // [128 n][3456 k]
__device__ half_t g_w3h[CH_IN * PP],      g_w3l[CH_IN * PP];        // [512 n][128 k]
__device__ float  g_valid[NPTS];
__device__ float  g_ratio[NPTS];
__device__ float  g_m2[NPTS];
__device__ float  g_part[(size_t)RBLK * CH_IN * 2];
__device__ float  g_mu[CH_IN];
__device__ float  g_rs[CH_IN];

// ---------------- PTX helpers ------------------------------------------------
__device__ __forceinline__ uint32_t smem_u32(const void* p) {
    uint32_t a;
    asm("{ .reg .u64 t; cvta.to.shared.u64 t, %1; cvt.u32.u64 %0, t; }" : "=r"(a) : "l"(p));
    return a;
}
#define CP16(dst, src) asm volatile("cp.async.cg.shared.global [%0], [%1], 16;" :: "r"(dst), "l"(src) : "memory")
#define CP_COMMIT()    asm volatile("cp.async.commit_group;" ::: "memory")
#define CP_WAIT0()     asm volatile("cp.async.wait_group 0;" ::: "memory")
#define CP_WAIT1()     asm volatile("cp.async.wait_group 1;" ::: "memory")

__device__ __forceinline__ void ldm4(uint32_t* r, uint32_t a) {
    asm volatile("ldmatrix.sync.aligned.m8n8.x4.shared.b16 {%0,%1,%2,%3}, [%4];"
                 : "=r"(r[0]), "=r"(r[1]), "=r"(r[2]), "=r"(r[3]) : "r"(a));
}
__device__ __forceinline__ void mma16816(float* c, const uint32_t* a, const uint32_t* b) {
    asm volatile("mma.sync.aligned.m16n8k16.row.col.f32.f16.f16.f32 "
                 "{%0,%1,%2,%3}, {%4,%5,%6,%7}, {%8,%9}, {%0,%1,%2,%3};"
                 : "+f"(c[0]), "+f"(c[1]), "+f"(c[2]), "+f"(c[3])
                 : "r"(a[0]), "r"(a[1]), "r"(a[2]), "r"(a[3]), "r"(b[0]), "r"(b[1]));
}
__device__ __forceinline__ void split2(float v, half_t& h, half_t& l) {
    h = __float2half_rn(v);
    l = __float2half_rn(v - __half2float(h));
}

// ---------------- small kernels ----------------------------------------------
__global__ void valid_kernel(const float* __restrict__ mask) {
    int n = blockIdx.x * blockDim.x + threadIdx.x;
    if (n < NPTS) g_valid[n] = mask[n] > 0.f ? 1.f : 0.f;
}
__global__ void ratio_kernel(const float* __restrict__ mask, const int* __restrict__ nbr,
                             float* __restrict__ mout) {
    int n = blockIdx.x * blockDim.x + threadIdx.x;
    if (n >= NPTS) return;
    float s = 0.f;
#pragma unroll
    for (int k = 0; k < KNB; k++) s += g_valid[nbr[(size_t)n * KNB + k]];
    float has = s > 0.f ? 1.f : 0.f;
    g_ratio[n] = has * (27.f / fmaxf(s, 1.f));
    g_m2[n] = has;
    mout[n] = fminf(has + mask[n], 1.f);
}
__global__ void convert_x(const float* __restrict__ x) {
    size_t i = (size_t)blockIdx.x * blockDim.x + threadIdx.x;
    if (i < (size_t)NPTS * CH_IN) split2(x[i], g_xh[i], g_xl[i]);
}
__global__ void prep_w1(const float* __restrict__ W1) {   // [512,128] -> [128 n][512 k]
    int i = blockIdx.x * blockDim.x + threadIdx.x;
    if (i >= PP * CH_IN) return;
    int n = i / CH_IN, k = i % CH_IN;
    split2(W1[(size_t)k * PP + n], g_w1h[i], g_w1l[i]);
}
__global__ void prep_w2(const float* __restrict__ W2) {   // [27,128,128] -> [128 n][3456 k]
    int i = blockIdx.x * blockDim.x + threadIdx.x;
    if (i >= PP * KNB * PP) return;
    int n = i / (KNB * PP), kk = i % (KNB * PP);
    split2(W2[(size_t)kk * PP + n], g_w2h[i], g_w2l[i]);
}
__global__ void prep_w3(const float* __restrict__ W3) {   // [128,512] -> [512 n][128 k]
    int i = blockIdx.x * blockDim.x + threadIdx.x;
    if (i >= CH_IN * PP) return;
    int n = i / PP, k = i % PP;
    split2(W3[(size_t)k * CH_IN + n], g_w3h[i], g_w3l[i]);
}
__global__ void stats_partial(const float* __restrict__ X, int C, int M) {
    int c = threadIdx.x;
    int per = (M + gridDim.x - 1) / gridDim.x;
    int r0 = blockIdx.x * per, r1 = min(r0 + per, M);
    float s = 0.f, q = 0.f;
    for (int r = r0; r < r1; r++) {
        float v = X[(size_t)r * C + c];
        s += v; q += v * v;
    }
    g_part[((size_t)blockIdx.x * C + c) * 2 + 0] = s;
    g_part[((size_t)blockIdx.x * C + c) * 2 + 1] = q;
}
__global__ void stats_final(int C, int M) {
    int c = threadIdx.x;
    float s = 0.f, q = 0.f;
    for (int r = 0; r < RBLK; r++) {
        s += g_part[((size_t)r * C + c) * 2 + 0];
        q += g_part[((size_t)r * C + c) * 2 + 1];
    }
    float mu = s / (float)M;
    float var = q / (float)M - mu * mu;
    g_mu[c] = mu;
    g_rs[c] = rsqrtf(fmaxf(var, 0.f) + EPSV);
}
__global__ void ew_split(const float* __restrict__ in, int use_mask) {
    int idx = blockIdx.x * blockDim.x + threadIdx.x;
    if (idx >= NPTS * PP) return;
    int c = idx & (PP - 1);
    int n = idx >> 7;
    float v = (in[idx] - g_mu[c]) * g_rs[c];
    v = v >= 0.f ? v : 0.1f * v;
    if (use_mask) v *= g_valid[n];
    split2(v, g_hh[idx], g_hl[idx]);
}
__global__ void ew_final(const float* __restrict__ x, float* __restrict__ outp) {
    size_t idx = (size_t)blockIdx.x * blockDim.x + threadIdx.x;
    if (idx >= (size_t)NPTS * CH_IN) return;
    int c = (int)(idx & (CH_IN - 1));
    float v = (outp[idx] - g_mu[c]) * g_rs[c] + x[idx];
    outp[idx] = v >= 0.f ? v : 0.1f * v;
}

// ---------------- HMMA GEMM --------------------------------------------------
// C[M,N] = A[M,Kd] @ B[N,Kd]^T  with fp16 hi/lo split (3 MMAs per k-step), fp32 acc.
// 128x128 CTA tile, 8 warps of 64x32, K-chunk 64, 2-stage cp.async pipeline.
// If nbr != null: A row r, K pos (kn*128 + c) reads Ah[nbr[r*27+kn]*lda + c].
#define STAGE_BYTES 65536
#define OFF_AL 16384u
#define OFF_B  32768u
#define OFF_BL 16384u
#define OFF_SN 131072u
#define SMEM_DYN (131072 + 128 * KNB * 4)

__global__ __launch_bounds__(256, 1) void mma_gemm(
    const half_t* __restrict__ Ah, const half_t* __restrict__ Al, int lda,
    const int* __restrict__ nbr,
    const half_t* __restrict__ Bh, const half_t* __restrict__ Bl, int ldb,
    float* __restrict__ C, int ldc, int M, int Kd,
    const float* __restrict__ rowscale) {
    extern __shared__ char smem[];
    const uint32_t sb = smem_u32(smem);
    const int tid = threadIdx.x;
    const int row0 = blockIdx.y * 128;
    const int col0 = blockIdx.x * 128;
    int* snbr = (int*)(smem + OFF_SN);

    if (nbr) {
        for (int i = tid; i < 128 * KNB; i += 256) {
            int r = i / KNB, k = i - r * KNB;
            int gr = row0 + r;
            snbr[i] = (gr < M) ? nbr[(size_t)gr * KNB + k] : 0;
        }
        __syncthreads();
    }

    const int w = tid >> 5, l = tid & 31;
    const int wm = (w & 1) * 64, wn = (w >> 1) * 32;
    const int a7 = l & 7, b7 = l & 7;
    const int lkA = (l >> 4) & 1, lkB = (l >> 3) & 1;
    uint32_t aRow[4], bRow[2];
#pragma unroll
    for (int i = 0; i < 4; i++) aRow[i] = (uint32_t)(wm + 16 * i + (l & 15)) << 7;
#pragma unroll
    for (int j = 0; j < 2; j++) bRow[j] = (uint32_t)(wn + 16 * j + (l & 7) + ((l & 16) >> 1)) << 7;

    float acc[4][4][4];
#pragma unroll
    for (int i = 0; i < 4; i++)
#pragma unroll
        for (int n = 0; n < 4; n++)
#pragma unroll
            for (int q = 0; q < 4; q++) acc[i][n][q] = 0.f;

    const int nch = Kd >> 6;

    auto load_chunk = [&](int ch, int stage) {
        const int k0 = ch << 6;
        const int kn = ch >> 1;
        const int c0 = (ch & 1) << 6;
        const uint32_t sbase = sb + stage * STAGE_BYTES;
        for (int i = tid; i < 1024; i += 256) {
            const int r = i >> 3, seg = i & 7;
            const uint32_t sw = ((uint32_t)r << 7) + (uint32_t)((seg ^ (r & 7)) << 4);
            size_t arow, acol;
            if (nbr) { arow = (size_t)snbr[r * KNB + kn]; acol = c0; }
            else     { arow = (size_t)min(row0 + r, M - 1); acol = k0; }
            const size_t ao = arow * (size_t)lda + acol + (seg << 3);
            CP16(sbase + sw,          Ah + ao);
            CP16(sbase + OFF_AL + sw, Al + ao);
            const size_t bo = (size_t)(col0 + r) * (size_t)ldb + k0 + (seg << 3);
            CP16(sbase + OFF_B + sw,          Bh + bo);
            CP16(sbase + OFF_B + OFF_BL + sw, Bl + bo);
        }
    };

    load_chunk(0, 0);
    CP_COMMIT();

    for (int ch = 0; ch < nch; ch++) {
        const int st = ch & 1;
        if (ch + 1 < nch) { load_chunk(ch + 1, st ^ 1); CP_COMMIT(); CP_WAIT1(); }
        else              { CP_WAIT0(); }
        __syncthreads();

        const uint32_t bA = sb + st * STAGE_BYTES;
        const uint32_t bB = bA + OFF_B;
#pragma unroll
        for (int s = 0; s < 4; s++) {
            uint32_t ah[4][4], al[4][4], bh[2][4], bl[2][4];
            const uint32_t kwA = (uint32_t)((s << 1) | lkA);
            const uint32_t kwB = (uint32_t)((s << 1) | lkB);
#pragma unroll
            for (int i = 0; i < 4; i++) {
                const uint32_t ad = bA + aRow[i] + ((kwA ^ (uint32_t)a7) << 4);
                ldm4(ah[i], ad);
                ldm4(al[i], ad + OFF_AL);
            }
#pragma unroll
            for (int j = 0; j < 2; j++) {
                const uint32_t bd = bB + bRow[j] + ((kwB ^ (uint32_t)b7) << 4);
                ldm4(bh[j], bd);
                ldm4(bl[j], bd + OFF_BL);
            }
#pragma unroll
            for (int i = 0; i < 4; i++)
#pragma unroll
                for (int n = 0; n < 4; n++)
                    mma16816(acc[i][n], ah[i], &bh[n >> 1][(n & 1) * 2]);
#pragma unroll
            for (int i = 0; i < 4; i++)
#pragma unroll
                for (int n = 0; n < 4; n++)
                    mma16816(acc[i][n], ah[i], &bl[n >> 1][(n & 1) * 2]);
#pragma unroll
            for (int i = 0; i < 4; i++)
#pragma unroll
                for (int n = 0; n < 4; n++)
                    mma16816(acc[i][n], al[i], &bh[n >> 1][(n & 1) * 2]);
        }
        __syncthreads();
    }

    // epilogue: *rowscale, store fp32
#pragma unroll
    for (int i = 0; i < 4; i++) {
        const int rb = row0 + wm + 16 * i + (l >> 2);
#pragma unroll
        for (int hf = 0; hf < 2; hf++) {
            const int r = rb + 8 * hf;
            if (r < M) {
                const float sc = rowscale[r];
                float* cp = C + (size_t)r * ldc + col0 + wn + 2 * (l & 3);
#pragma unroll
                for (int n = 0; n < 4; n++) {
                    float2 v = make_float2(acc[i][n][2 * hf] * sc, acc[i][n][2 * hf + 1] * sc);
                    *(float2*)(cp + 8 * n) = v;
                }
            }
        }
    }
}

// ---------------- launch ------------------------------------------------------
extern "C" void kernel_launch(void* const* d_in, const int* in_sizes, int n_in,
                              void* d_out, int out_size) {
    const float* x    = (const float*)d_in[0];
    const float* mask = (const float*)d_in[1];
    const int*   nbr  = (const int*)d_in[2];
    const float* W1   = (const float*)d_in[3];
    const float* W2   = (const float*)d_in[4];
    const float* W3   = (const float*)d_in[5];
    float* out  = (float*)d_out;
    float* mout = out + (size_t)NPTS * CH_IN;

    cudaFuncSetAttribute(mma_gemm, cudaFuncAttributeMaxDynamicSharedMemorySize, SMEM_DYN);

    float *pA, *pValid, *pRatio, *pM2;
    half_t *pxh, *pxl, *phh, *phl, *pw1h, *pw1l, *pw2h, *pw2l, *pw3h, *pw3l;
    cudaGetSymbolAddress((void**)&pA, g_bufA);
    cudaGetSymbolAddress((void**)&pValid, g_valid);
    cudaGetSymbolAddress((void**)&pRatio, g_ratio);
    cudaGetSymbolAddress((void**)&pM2, g_m2);
    cudaGetSymbolAddress((void**)&pxh, g_xh);
    cudaGetSymbolAddress((void**)&pxl, g_xl);
    cudaGetSymbolAddress((void**)&phh, g_hh);
    cudaGetSymbolAddress((void**)&phl, g_hl);
    cudaGetSymbolAddress((void**)&pw1h, g_w1h);
    cudaGetSymbolAddress((void**)&pw1l, g_w1l);
    cudaGetSymbolAddress((void**)&pw2h, g_w2h);
    cudaGetSymbolAddress((void**)&pw2l, g_w2l);
    cudaGetSymbolAddress((void**)&pw3h, g_w3h);
    cudaGetSymbolAddress((void**)&pw3l, g_w3l);

    const int nb = (NPTS + 255) / 256;
    valid_kernel<<<nb, 256>>>(mask);
    ratio_kernel<<<nb, 256>>>(mask, nbr, mout);
    convert_x<<<(int)(((size_t)NPTS * CH_IN + 255) / 256), 256>>>(x);
    prep_w1<<<(PP * CH_IN + 255) / 256, 256>>>(W1);
    prep_w2<<<(PP * KNB * PP + 255) / 256, 256>>>(W2);
    prep_w3<<<(CH_IN * PP + 255) / 256, 256>>>(W3);

    const int nrt = (NPTS + 127) / 128;   // 391
    // conv1: t1 = (x @ W1) * valid
    mma_gemm<<<dim3(1, nrt), 256, SMEM_DYN>>>(pxh, pxl, CH_IN, nullptr,
                                              pw1h, pw1l, CH_IN, pA, PP, NPTS, CH_IN, pValid);
    stats_partial<<<RBLK, PP>>>(pA, PP, NPTS);
    stats_final<<<1, PP>>>(PP, NPTS);
    ew_split<<<(NPTS * PP + 255) / 256, 256>>>(pA, 1);

    // conv2 gathered: Kd = 27*128 = 3456
    mma_gemm<<<dim3(1, nrt), 256, SMEM_DYN>>>(phh, phl, PP, nbr,
                                              pw2h, pw2l, KNB * PP, pA, PP, NPTS, KNB * PP, pRatio);
    stats_partial<<<RBLK, PP>>>(pA, PP, NPTS);
    stats_final<<<1, PP>>>(PP, NPTS);
    ew_split<<<(NPTS * PP + 255) / 256, 256>>>(pA, 0);

    // conv3: out = (h2 @ W3) * m2   (N=512 via 4 column tiles)
    mma_gemm<<<dim3(4, nrt), 256, SMEM_DYN>>>(phh, phl, PP, nullptr,
                                              pw3h, pw3l, PP, out, CH_IN, NPTS, PP, pM2);
    stats_partial<<<RBLK, CH_IN>>>(out, CH_IN, NPTS);
    stats_final<<<1, CH_IN>>>(CH_IN, NPTS);
    ew_final<<<(int)(((size_t)NPTS * CH_IN + 255) / 256), 256>>>(x, out);
}

// round 5
// speedup vs baseline: 3.0110x; 1.2344x over previous
#include <cuda_runtime.h>
#include <cuda_fp16.h>
#include <cstdint>

#define NPTS 50000
#define CH_IN 512
#define PP 128
#define KNB 27
#define EPSV 1e-5f

typedef __half half_t;

#define NROWT ((NPTS + 127) / 128)   // 391 row tiles

// ---------------- scratch (device globals) ----------------------------------
__device__ float  g_bufA[(size_t)NPTS * PP];
__device__ half_t g_xh[(size_t)NPTS * CH_IN];
__device__ half_t g_hh[(size_t)NPTS * PP];
__device__ half_t g_w1h[PP * CH_IN],    g_w1l[PP * CH_IN];      // [128 n][512 k]
__device__ half_t g_w2h[PP * KNB * PP], g_w2l[PP * KNB * PP];   // [128 n][3456 k]
__device__ half_t g_w3h[CH_IN * PP],    g_w3l[CH_IN * PP];      // [512 n][128 k]
__device__ float  g_valid[NPTS];
__device__ float  g_ratio[NPTS];
__device__ float  g_m2[NPTS];
__device__ float2 g_part2[(size_t)NROWT * CH_IN];
__device__ float  g_mu[CH_IN];
__device__ float  g_rs[CH_IN];

// ---------------- PTX helpers ------------------------------------------------
__device__ __forceinline__ uint32_t smem_u32(const void* p) {
    uint32_t a;
    asm("{ .reg .u64 t; cvta.to.shared.u64 t, %1; cvt.u32.u64 %0, t; }" : "=r"(a) : "l"(p));
    return a;
}
#define CP16(dst, src) asm volatile("cp.async.cg.shared.global [%0], [%1], 16;" :: "r"(dst), "l"(src) : "memory")
#define CP_COMMIT()    asm volatile("cp.async.commit_group;" ::: "memory")
#define CP_WAIT0()     asm volatile("cp.async.wait_group 0;" ::: "memory")
#define CP_WAIT1()     asm volatile("cp.async.wait_group 1;" ::: "memory")
#define CP_WAIT2()     asm volatile("cp.async.wait_group 2;" ::: "memory")

__device__ __forceinline__ void ldm4(uint32_t* r, uint32_t a) {
    asm volatile("ldmatrix.sync.aligned.m8n8.x4.shared.b16 {%0,%1,%2,%3}, [%4];"
                 : "=r"(r[0]), "=r"(r[1]), "=r"(r[2]), "=r"(r[3]) : "r"(a));
}
__device__ __forceinline__ void mma16816(float* c, const uint32_t* a, const uint32_t* b) {
    asm volatile("mma.sync.aligned.m16n8k16.row.col.f32.f16.f16.f32 "
                 "{%0,%1,%2,%3}, {%4,%5,%6,%7}, {%8,%9}, {%0,%1,%2,%3};"
                 : "+f"(c[0]), "+f"(c[1]), "+f"(c[2]), "+f"(c[3])
                 : "r"(a[0]), "r"(a[1]), "r"(a[2]), "r"(a[3]), "r"(b[0]), "r"(b[1]));
}
__device__ __forceinline__ void split2(float v, half_t& h, half_t& l) {
    h = __float2half_rn(v);
    l = __float2half_rn(v - __half2float(h));
}

// ---------------- small kernels ----------------------------------------------
__global__ void valid_kernel(const float* __restrict__ mask) {
    int n = blockIdx.x * blockDim.x + threadIdx.x;
    if (n < NPTS) g_valid[n] = mask[n] > 0.f ? 1.f : 0.f;
}
__global__ void ratio_kernel(const float* __restrict__ mask, const int* __restrict__ nbr,
                             float* __restrict__ mout) {
    int n = blockIdx.x * blockDim.x + threadIdx.x;
    if (n >= NPTS) return;
    float s = 0.f;
#pragma unroll
    for (int k = 0; k < KNB; k++) s += g_valid[nbr[(size_t)n * KNB + k]];
    float has = s > 0.f ? 1.f : 0.f;
    g_ratio[n] = has * (27.f / fmaxf(s, 1.f));
    g_m2[n] = has;
    mout[n] = fminf(has + mask[n], 1.f);
}
__global__ void convert_x(const float* __restrict__ x) {
    size_t i = (size_t)blockIdx.x * blockDim.x + threadIdx.x;
    if (i < (size_t)NPTS * CH_IN) g_xh[i] = __float2half_rn(x[i]);
}
// all weight preps in one kernel; B-side keeps hi/lo split
#define W1E (PP * CH_IN)
#define W2E (PP * KNB * PP)
#define W3E (CH_IN * PP)
__global__ void prep_w(const float* __restrict__ W1, const float* __restrict__ W2,
                       const float* __restrict__ W3) {
    int i = blockIdx.x * blockDim.x + threadIdx.x;
    if (i < W1E) {                    // [512,128] -> [128 n][512 k]
        int n = i / CH_IN, k = i % CH_IN;
        split2(W1[(size_t)k * PP + n], g_w1h[i], g_w1l[i]);
    } else if (i < W1E + W2E) {       // [27*128,128] -> [128 n][3456 k]
        int j = i - W1E;
        int n = j / (KNB * PP), kk = j % (KNB * PP);
        split2(W2[(size_t)kk * PP + n], g_w2h[j], g_w2l[j]);
    } else if (i < W1E + W2E + W3E) { // [128,512] -> [512 n][128 k]
        int j = i - W1E - W2E;
        int n = j / PP, k = j % PP;
        split2(W3[(size_t)k * CH_IN + n], g_w3h[j], g_w3l[j]);
    }
}
__global__ void stats_final(const float2* __restrict__ part, int C, int M, int nslots) {
    int c = threadIdx.x;
    float s = 0.f, q = 0.f;
    for (int r = 0; r < nslots; r++) {
        float2 v = part[(size_t)r * C + c];
        s += v.x; q += v.y;
    }
    float mu = s / (float)M;
    float var = q / (float)M - mu * mu;
    g_mu[c] = mu;
    g_rs[c] = rsqrtf(fmaxf(var, 0.f) + EPSV);
}
__global__ void ew_split(const float* __restrict__ in, int use_mask) {
    int idx = blockIdx.x * blockDim.x + threadIdx.x;
    if (idx >= NPTS * PP) return;
    int c = idx & (PP - 1);
    int n = idx >> 7;
    float v = (in[idx] - g_mu[c]) * g_rs[c];
    v = v >= 0.f ? v : 0.1f * v;
    if (use_mask) v *= g_valid[n];
    g_hh[idx] = __float2half_rn(v);
}
__global__ void ew_final(const float* __restrict__ x, float* __restrict__ outp) {
    size_t idx = (size_t)blockIdx.x * blockDim.x + threadIdx.x;
    if (idx >= (size_t)NPTS * CH_IN) return;
    int c = (int)(idx & (CH_IN - 1));
    float v = (outp[idx] - g_mu[c]) * g_rs[c] + x[idx];
    outp[idx] = v >= 0.f ? v : 0.1f * v;
}

// ---------------- HMMA GEMM --------------------------------------------------
// C[M,N] = A[M,Kd] @ B[N,Kd]^T ; A fp16 (hi only), B fp16 hi/lo (2 MMAs/k-step),
// fp32 acc. 128x128 CTA tile, 8 warps of 64x32, K-chunk 64, 3-stage cp.async.
// Fused epilogue: *rowscale, store, and deterministic per-CTA column sum/sumsq
// partials into part[by*partC + col0 + c].
#define STAGE_BYTES 49152
#define OFF_BH 16384u
#define OFF_BL 32768u
#define OFF_SN (3u * STAGE_BYTES)
#define SMEM_DYN (3 * STAGE_BYTES + 128 * KNB * 4)

__global__ __launch_bounds__(256, 1) void mma_gemm(
    const half_t* __restrict__ Ah, int lda,
    const int* __restrict__ nbr,
    const half_t* __restrict__ Bh, const half_t* __restrict__ Bl, int ldb,
    float* __restrict__ C, int ldc, int M, int Kd,
    const float* __restrict__ rowscale,
    float2* __restrict__ part, int partC) {
    extern __shared__ char smem[];
    const uint32_t sb = smem_u32(smem);
    const int tid = threadIdx.x;
    const int row0 = blockIdx.y * 128;
    const int col0 = blockIdx.x * 128;
    int* snbr = (int*)(smem + OFF_SN);

    if (nbr) {
        for (int i = tid; i < 128 * KNB; i += 256) {
            int r = i / KNB, k = i - r * KNB;
            int gr = row0 + r;
            snbr[i] = (gr < M) ? nbr[(size_t)gr * KNB + k] : 0;
        }
        __syncthreads();
    }

    const int w = tid >> 5, l = tid & 31;
    const int wm = (w & 1) * 64, wn = (w >> 1) * 32;
    const int a7 = l & 7;
    const int lkA = (l >> 4) & 1, lkB = (l >> 3) & 1;
    uint32_t aRow[4], bRow[2];
#pragma unroll
    for (int i = 0; i < 4; i++) aRow[i] = (uint32_t)(wm + 16 * i + (l & 15)) << 7;
#pragma unroll
    for (int j = 0; j < 2; j++) bRow[j] = (uint32_t)(wn + 16 * j + (l & 7) + ((l & 16) >> 1)) << 7;

    float acc[4][4][4];
#pragma unroll
    for (int i = 0; i < 4; i++)
#pragma unroll
        for (int n = 0; n < 4; n++)
#pragma unroll
            for (int q = 0; q < 4; q++) acc[i][n][q] = 0.f;

    const int nch = Kd >> 6;

    auto load_chunk = [&](int ch, int stage) {
        const int k0 = ch << 6;
        const int kn = ch >> 1;
        const int c0 = (ch & 1) << 6;
        const uint32_t sbase = sb + (uint32_t)stage * STAGE_BYTES;
        for (int i = tid; i < 1024; i += 256) {
            const int r = i >> 3, seg = i & 7;
            const uint32_t sw = ((uint32_t)r << 7) + (uint32_t)((seg ^ (r & 7)) << 4);
            size_t arow, acol;
            if (nbr) { arow = (size_t)snbr[r * KNB + kn]; acol = c0; }
            else     { arow = (size_t)min(row0 + r, M - 1); acol = k0; }
            CP16(sbase + sw, Ah + arow * (size_t)lda + acol + (seg << 3));
            const size_t bo = (size_t)(col0 + r) * (size_t)ldb + k0 + (seg << 3);
            CP16(sbase + OFF_BH + sw, Bh + bo);
            CP16(sbase + OFF_BL + sw, Bl + bo);
        }
    };

    load_chunk(0, 0);
    CP_COMMIT();
    if (nch > 1) { load_chunk(1, 1); CP_COMMIT(); }

    for (int ch = 0; ch < nch; ch++) {
        const int st = ch % 3;
        if (ch + 2 < nch)      { load_chunk(ch + 2, (ch + 2) % 3); CP_COMMIT(); CP_WAIT2(); }
        else if (ch + 1 < nch) { CP_WAIT1(); }
        else                   { CP_WAIT0(); }
        __syncthreads();

        const uint32_t bA = sb + (uint32_t)st * STAGE_BYTES;
#pragma unroll
        for (int s = 0; s < 4; s++) {
            uint32_t ah[4][4], bh[2][4], bl[2][4];
            const uint32_t kwA = (uint32_t)((s << 1) | lkA);
            const uint32_t kwB = (uint32_t)((s << 1) | lkB);
#pragma unroll
            for (int i = 0; i < 4; i++)
                ldm4(ah[i], bA + aRow[i] + ((kwA ^ (uint32_t)a7) << 4));
#pragma unroll
            for (int j = 0; j < 2; j++) {
                const uint32_t bd = bA + bRow[j] + ((kwB ^ (uint32_t)a7) << 4);
                ldm4(bh[j], bd + OFF_BH);
                ldm4(bl[j], bd + OFF_BL);
            }
#pragma unroll
            for (int i = 0; i < 4; i++)
#pragma unroll
                for (int n = 0; n < 4; n++)
                    mma16816(acc[i][n], ah[i], &bh[n >> 1][(n & 1) * 2]);
#pragma unroll
            for (int i = 0; i < 4; i++)
#pragma unroll
                for (int n = 0; n < 4; n++)
                    mma16816(acc[i][n], ah[i], &bl[n >> 1][(n & 1) * 2]);
        }
        __syncthreads();
    }

    // ---- fused epilogue: scale, store, per-CTA column partial stats ----
    float csum[8], csq[8];
#pragma unroll
    for (int j = 0; j < 8; j++) { csum[j] = 0.f; csq[j] = 0.f; }
#pragma unroll
    for (int i = 0; i < 4; i++) {
#pragma unroll
        for (int hf = 0; hf < 2; hf++) {
            const int r = row0 + wm + 16 * i + 8 * hf + (l >> 2);
            const float sc = (r < M) ? rowscale[r] : 0.f;
            float* cp = C + (size_t)r * ldc + col0 + wn + 2 * (l & 3);
#pragma unroll
            for (int n = 0; n < 4; n++) {
                float v0 = acc[i][n][2 * hf] * sc;
                float v1 = acc[i][n][2 * hf + 1] * sc;
                csum[2 * n]     += v0; csq[2 * n]     += v0 * v0;
                csum[2 * n + 1] += v1; csq[2 * n + 1] += v1 * v1;
                if (r < M) *(float2*)(cp + 8 * n) = make_float2(v0, v1);
            }
        }
    }
    // reduce over rows within warp (lanes sharing l&3)
#pragma unroll
    for (int d = 4; d < 32; d <<= 1) {
#pragma unroll
        for (int j = 0; j < 8; j++) {
            csum[j] += __shfl_xor_sync(0xFFFFFFFFu, csum[j], d);
            csq[j]  += __shfl_xor_sync(0xFFFFFFFFu, csq[j], d);
        }
    }
    float2* red = (float2*)(smem + OFF_SN);   // snbr no longer needed
    __syncthreads();
    if (l < 4) {
#pragma unroll
        for (int j = 0; j < 8; j++) {
            int col_local = 8 * (j >> 1) + 2 * l + (j & 1);
            red[w * 32 + col_local] = make_float2(csum[j], csq[j]);
        }
    }
    __syncthreads();
    if (tid < 128) {
        int c = tid, q = c >> 5, lo = c & 31;
        float2 a = red[(2 * q) * 32 + lo];
        float2 b = red[(2 * q + 1) * 32 + lo];
        part[(size_t)blockIdx.y * partC + col0 + c] = make_float2(a.x + b.x, a.y + b.y);
    }
}

// ---------------- launch ------------------------------------------------------
extern "C" void kernel_launch(void* const* d_in, const int* in_sizes, int n_in,
                              void* d_out, int out_size) {
    const float* x    = (const float*)d_in[0];
    const float* mask = (const float*)d_in[1];
    const int*   nbr  = (const int*)d_in[2];
    const float* W1   = (const float*)d_in[3];
    const float* W2   = (const float*)d_in[4];
    const float* W3   = (const float*)d_in[5];
    float* out  = (float*)d_out;
    float* mout = out + (size_t)NPTS * CH_IN;

    cudaFuncSetAttribute(mma_gemm, cudaFuncAttributeMaxDynamicSharedMemorySize, SMEM_DYN);

    float *pA, *pValid, *pRatio, *pM2;
    float2* pPart;
    half_t *pxh, *phh, *pw1h, *pw1l, *pw2h, *pw2l, *pw3h, *pw3l;
    cudaGetSymbolAddress((void**)&pA, g_bufA);
    cudaGetSymbolAddress((void**)&pValid, g_valid);
    cudaGetSymbolAddress((void**)&pRatio, g_ratio);
    cudaGetSymbolAddress((void**)&pM2, g_m2);
    cudaGetSymbolAddress((void**)&pPart, g_part2);
    cudaGetSymbolAddress((void**)&pxh, g_xh);
    cudaGetSymbolAddress((void**)&phh, g_hh);
    cudaGetSymbolAddress((void**)&pw1h, g_w1h);
    cudaGetSymbolAddress((void**)&pw1l, g_w1l);
    cudaGetSymbolAddress((void**)&pw2h, g_w2h);
    cudaGetSymbolAddress((void**)&pw2l, g_w2l);
    cudaGetSymbolAddress((void**)&pw3h, g_w3h);
    cudaGetSymbolAddress((void**)&pw3l, g_w3l);

    const int nb = (NPTS + 255) / 256;
    valid_kernel<<<nb, 256>>>(mask);
    ratio_kernel<<<nb, 256>>>(mask, nbr, mout);
    convert_x<<<(int)(((size_t)NPTS * CH_IN + 255) / 256), 256>>>(x);
    prep_w<<<(W1E + W2E + W3E + 255) / 256, 256>>>(W1, W2, W3);

    // conv1: t1 = (x @ W1) * valid   [Kd=512]
    mma_gemm<<<dim3(1, NROWT), 256, SMEM_DYN>>>(pxh, CH_IN, nullptr,
        pw1h, pw1l, CH_IN, pA, PP, NPTS, CH_IN, pValid, pPart, PP);
    stats_final<<<1, PP>>>(pPart, PP, NPTS, NROWT);
    ew_split<<<(NPTS * PP + 255) / 256, 256>>>(pA, 1);

    // conv2 gathered: Kd = 27*128 = 3456
    mma_gemm<<<dim3(1, NROWT), 256, SMEM_DYN>>>(phh, PP, nbr,
        pw2h, pw2l, KNB * PP, pA, PP, NPTS, KNB * PP, pRatio, pPart, PP);
    stats_final<<<1, PP>>>(pPart, PP, NPTS, NROWT);
    ew_split<<<(NPTS * PP + 255) / 256, 256>>>(pA, 0);

    // conv3: out = (h2 @ W3) * m2   [N=512 via 4 column tiles, Kd=128]
    mma_gemm<<<dim3(4, NROWT), 256, SMEM_DYN>>>(phh, PP, nullptr,
        pw3h, pw3l, PP, out, CH_IN, NPTS, PP, pM2, pPart, CH_IN);
    stats_final<<<1, CH_IN>>>(pPart, CH_IN, NPTS, NROWT);
    ew_final<<<(int)(((size_t)NPTS * CH_IN + 255) / 256), 256>>>(x, out);
}

// round 6
// speedup vs baseline: 4.1264x; 1.3704x over previous
#include <cuda_runtime.h>
#include <cuda_fp16.h>
#include <cstdint>

#define NPTS 50000
#define CH_IN 512
#define PP 128
#define KNB 27
#define EPSV 1e-5f

typedef __half half_t;

#define NROWT ((NPTS + 127) / 128)   // 391 row tiles

// ---------------- scratch (device globals) ----------------------------------
__device__ float  g_bufA[(size_t)NPTS * PP];
__device__ half_t g_xh[(size_t)NPTS * CH_IN];
__device__ half_t g_hh[(size_t)NPTS * PP];
__device__ half_t g_w1h[PP * CH_IN];        // [128 n][512 k]
__device__ half_t g_w2h[PP * KNB * PP];     // [128 n][3456 k]
__device__ half_t g_w3h[CH_IN * PP];        // [512 n][128 k]
__device__ float  g_valid[NPTS];
__device__ float  g_ratio[NPTS];
__device__ float  g_m2[NPTS];
__device__ float2 g_part2[(size_t)NROWT * CH_IN];
__device__ float  g_mu[CH_IN];
__device__ float  g_rs[CH_IN];

// ---------------- PTX helpers ------------------------------------------------
__device__ __forceinline__ uint32_t smem_u32(const void* p) {
    uint32_t a;
    asm("{ .reg .u64 t; cvta.to.shared.u64 t, %1; cvt.u32.u64 %0, t; }" : "=r"(a) : "l"(p));
    return a;
}
#define CP16(dst, src) asm volatile("cp.async.cg.shared.global [%0], [%1], 16;" :: "r"(dst), "l"(src) : "memory")
#define CP_COMMIT()    asm volatile("cp.async.commit_group;" ::: "memory")
#define CP_WAIT0()     asm volatile("cp.async.wait_group 0;" ::: "memory")
#define CP_WAIT1()     asm volatile("cp.async.wait_group 1;" ::: "memory")
#define CP_WAIT2()     asm volatile("cp.async.wait_group 2;" ::: "memory")

__device__ __forceinline__ void ldm4(uint32_t* r, uint32_t a) {
    asm volatile("ldmatrix.sync.aligned.m8n8.x4.shared.b16 {%0,%1,%2,%3}, [%4];"
                 : "=r"(r[0]), "=r"(r[1]), "=r"(r[2]), "=r"(r[3]) : "r"(a));
}
__device__ __forceinline__ void mma16816(float* c, const uint32_t* a, const uint32_t* b) {
    asm volatile("mma.sync.aligned.m16n8k16.row.col.f32.f16.f16.f32 "
                 "{%0,%1,%2,%3}, {%4,%5,%6,%7}, {%8,%9}, {%0,%1,%2,%3};"
                 : "+f"(c[0]), "+f"(c[1]), "+f"(c[2]), "+f"(c[3])
                 : "r"(a[0]), "r"(a[1]), "r"(a[2]), "r"(a[3]), "r"(b[0]), "r"(b[1]));
}

// ---------------- small kernels ----------------------------------------------
__global__ void valid_kernel(const float* __restrict__ mask) {
    int n = blockIdx.x * blockDim.x + threadIdx.x;
    if (n < NPTS) g_valid[n] = mask[n] > 0.f ? 1.f : 0.f;
}
__global__ void ratio_kernel(const float* __restrict__ mask, const int* __restrict__ nbr,
                             float* __restrict__ mout) {
    int n = blockIdx.x * blockDim.x + threadIdx.x;
    if (n >= NPTS) return;
    float s = 0.f;
#pragma unroll
    for (int k = 0; k < KNB; k++) s += g_valid[nbr[(size_t)n * KNB + k]];
    float has = s > 0.f ? 1.f : 0.f;
    g_ratio[n] = has * (27.f / fmaxf(s, 1.f));
    g_m2[n] = has;
    mout[n] = fminf(has + mask[n], 1.f);
}
__global__ void convert_x(const float* __restrict__ x) {
    size_t i = (size_t)blockIdx.x * blockDim.x + threadIdx.x;
    if (i < (size_t)NPTS * CH_IN) g_xh[i] = __float2half_rn(x[i]);
}
#define W1E (PP * CH_IN)
#define W2E (PP * KNB * PP)
#define W3E (CH_IN * PP)
__global__ void prep_w(const float* __restrict__ W1, const float* __restrict__ W2,
                       const float* __restrict__ W3) {
    int i = blockIdx.x * blockDim.x + threadIdx.x;
    if (i < W1E) {                    // [512,128] -> [128 n][512 k]
        int n = i / CH_IN, k = i % CH_IN;
        g_w1h[i] = __float2half_rn(W1[(size_t)k * PP + n]);
    } else if (i < W1E + W2E) {       // [27*128,128] -> [128 n][3456 k]
        int j = i - W1E;
        int n = j / (KNB * PP), kk = j % (KNB * PP);
        g_w2h[j] = __float2half_rn(W2[(size_t)kk * PP + n]);
    } else if (i < W1E + W2E + W3E) { // [128,512] -> [512 n][128 k]
        int j = i - W1E - W2E;
        int n = j / PP, k = j % PP;
        g_w3h[j] = __float2half_rn(W3[(size_t)k * CH_IN + n]);
    }
}
__global__ void stats_final(const float2* __restrict__ part, int C, int M, int nslots) {
    int c = threadIdx.x;
    float s = 0.f, q = 0.f;
    for (int r = 0; r < nslots; r++) {
        float2 v = part[(size_t)r * C + c];
        s += v.x; q += v.y;
    }
    float mu = s / (float)M;
    float var = q / (float)M - mu * mu;
    g_mu[c] = mu;
    g_rs[c] = rsqrtf(fmaxf(var, 0.f) + EPSV);
}
__global__ void ew_split(const float* __restrict__ in, int use_mask) {
    int idx = blockIdx.x * blockDim.x + threadIdx.x;
    if (idx >= NPTS * PP) return;
    int c = idx & (PP - 1);
    int n = idx >> 7;
    float v = (in[idx] - g_mu[c]) * g_rs[c];
    v = v >= 0.f ? v : 0.1f * v;
    if (use_mask) v *= g_valid[n];
    g_hh[idx] = __float2half_rn(v);
}
__global__ void ew_final(const float* __restrict__ x, float* __restrict__ outp) {
    size_t idx = (size_t)blockIdx.x * blockDim.x + threadIdx.x;
    if (idx >= (size_t)NPTS * CH_IN) return;
    int c = (int)(idx & (CH_IN - 1));
    float v = (outp[idx] - g_mu[c]) * g_rs[c] + x[idx];
    outp[idx] = v >= 0.f ? v : 0.1f * v;
}

// ---------------- HMMA GEMM --------------------------------------------------
// C[M,N] = A[M,Kd] @ B[N,Kd]^T, fp16 operands, fp32 acc.
// 128x128 CTA tile, 8 warps of 64x32, K-chunk 64, 3-stage cp.async, 2 CTAs/SM.
// Fused epilogue: *rowscale, store, deterministic per-CTA column sum/sumsq.
#define STAGE_BYTES 32768
#define OFF_B  16384u
#define OFF_SN (3u * STAGE_BYTES)
#define SMEM_DYN (3 * STAGE_BYTES + 128 * KNB * 4)

__global__ __launch_bounds__(256, 2) void mma_gemm(
    const half_t* __restrict__ Ah, int lda,
    const int* __restrict__ nbr,
    const half_t* __restrict__ Bh, int ldb,
    float* __restrict__ C, int ldc, int M, int Kd,
    const float* __restrict__ rowscale,
    float2* __restrict__ part, int partC) {
    extern __shared__ char smem[];
    const uint32_t sb = smem_u32(smem);
    const int tid = threadIdx.x;
    const int row0 = blockIdx.y * 128;
    const int col0 = blockIdx.x * 128;
    int* snbr = (int*)(smem + OFF_SN);

    if (nbr) {
        for (int i = tid; i < 128 * KNB; i += 256) {
            int r = i / KNB, k = i - r * KNB;
            int gr = row0 + r;
            snbr[i] = (gr < M) ? nbr[(size_t)gr * KNB + k] : 0;
        }
        __syncthreads();
    }

    const int w = tid >> 5, l = tid & 31;
    const int wm = (w & 1) * 64, wn = (w >> 1) * 32;
    const int a7 = l & 7;
    const int lkA = (l >> 4) & 1, lkB = (l >> 3) & 1;
    uint32_t aRow[4], bRow[2];
#pragma unroll
    for (int i = 0; i < 4; i++) aRow[i] = (uint32_t)(wm + 16 * i + (l & 15)) << 7;
#pragma unroll
    for (int j = 0; j < 2; j++) bRow[j] = (uint32_t)(wn + 16 * j + (l & 7) + ((l & 16) >> 1)) << 7;

    float acc[4][4][4];
#pragma unroll
    for (int i = 0; i < 4; i++)
#pragma unroll
        for (int n = 0; n < 4; n++)
#pragma unroll
            for (int q = 0; q < 4; q++) acc[i][n][q] = 0.f;

    const int nch = Kd >> 6;

    auto load_chunk = [&](int ch, int stage) {
        const int k0 = ch << 6;
        const int kn = ch >> 1;
        const int c0 = (ch & 1) << 6;
        const uint32_t sbase = sb + (uint32_t)stage * STAGE_BYTES;
        for (int i = tid; i < 1024; i += 256) {
            const int r = i >> 3, seg = i & 7;
            const uint32_t sw = ((uint32_t)r << 7) + (uint32_t)((seg ^ (r & 7)) << 4);
            size_t arow, acol;
            if (nbr) { arow = (size_t)snbr[r * KNB + kn]; acol = c0; }
            else     { arow = (size_t)min(row0 + r, M - 1); acol = k0; }
            CP16(sbase + sw, Ah + arow * (size_t)lda + acol + (seg << 3));
            CP16(sbase + OFF_B + sw, Bh + (size_t)(col0 + r) * (size_t)ldb + k0 + (seg << 3));
        }
    };

    load_chunk(0, 0);
    CP_COMMIT();
    if (nch > 1) { load_chunk(1, 1); CP_COMMIT(); }

    for (int ch = 0; ch < nch; ch++) {
        const int st = ch % 3;
        if (ch + 2 < nch)      { load_chunk(ch + 2, (ch + 2) % 3); CP_COMMIT(); CP_WAIT2(); }
        else if (ch + 1 < nch) { CP_WAIT1(); }
        else                   { CP_WAIT0(); }
        __syncthreads();

        const uint32_t bA = sb + (uint32_t)st * STAGE_BYTES;
#pragma unroll
        for (int s = 0; s < 4; s++) {
            uint32_t ah[4][4], bh[2][4];
            const uint32_t kwA = (uint32_t)((s << 1) | lkA);
            const uint32_t kwB = (uint32_t)((s << 1) | lkB);
#pragma unroll
            for (int i = 0; i < 4; i++)
                ldm4(ah[i], bA + aRow[i] + ((kwA ^ (uint32_t)a7) << 4));
#pragma unroll
            for (int j = 0; j < 2; j++)
                ldm4(bh[j], bA + OFF_B + bRow[j] + ((kwB ^ (uint32_t)a7) << 4));
#pragma unroll
            for (int i = 0; i < 4; i++)
#pragma unroll
                for (int n = 0; n < 4; n++)
                    mma16816(acc[i][n], ah[i], &bh[n >> 1][(n & 1) * 2]);
        }
        __syncthreads();
    }

    // ---- fused epilogue: scale, store, per-CTA column partial stats ----
    float csum[8], csq[8];
#pragma unroll
    for (int j = 0; j < 8; j++) { csum[j] = 0.f; csq[j] = 0.f; }
#pragma unroll
    for (int i = 0; i < 4; i++) {
#pragma unroll
        for (int hf = 0; hf < 2; hf++) {
            const int r = row0 + wm + 16 * i + 8 * hf + (l >> 2);
            const float sc = (r < M) ? rowscale[r] : 0.f;
            float* cp = C + (size_t)r * ldc + col0 + wn + 2 * (l & 3);
#pragma unroll
            for (int n = 0; n < 4; n++) {
                float v0 = acc[i][n][2 * hf] * sc;
                float v1 = acc[i][n][2 * hf + 1] * sc;
                csum[2 * n]     += v0; csq[2 * n]     += v0 * v0;
                csum[2 * n + 1] += v1; csq[2 * n + 1] += v1 * v1;
                if (r < M) *(float2*)(cp + 8 * n) = make_float2(v0, v1);
            }
        }
    }
#pragma unroll
    for (int d = 4; d < 32; d <<= 1) {
#pragma unroll
        for (int j = 0; j < 8; j++) {
            csum[j] += __shfl_xor_sync(0xFFFFFFFFu, csum[j], d);
            csq[j]  += __shfl_xor_sync(0xFFFFFFFFu, csq[j], d);
        }
    }
    float2* red = (float2*)(smem + OFF_SN);   // snbr no longer needed
    __syncthreads();
    if (l < 4) {
#pragma unroll
        for (int j = 0; j < 8; j++) {
            int col_local = 8 * (j >> 1) + 2 * l + (j & 1);
            red[w * 32 + col_local] = make_float2(csum[j], csq[j]);
        }
    }
    __syncthreads();
    if (tid < 128) {
        int c = tid, q = c >> 5, lo = c & 31;
        float2 a = red[(2 * q) * 32 + lo];
        float2 b = red[(2 * q + 1) * 32 + lo];
        part[(size_t)blockIdx.y * partC + col0 + c] = make_float2(a.x + b.x, a.y + b.y);
    }
}

// ---------------- launch ------------------------------------------------------
extern "C" void kernel_launch(void* const* d_in, const int* in_sizes, int n_in,
                              void* d_out, int out_size) {
    const float* x    = (const float*)d_in[0];
    const float* mask = (const float*)d_in[1];
    const int*   nbr  = (const int*)d_in[2];
    const float* W1   = (const float*)d_in[3];
    const float* W2   = (const float*)d_in[4];
    const float* W3   = (const float*)d_in[5];
    float* out  = (float*)d_out;
    float* mout = out + (size_t)NPTS * CH_IN;

    cudaFuncSetAttribute(mma_gemm, cudaFuncAttributeMaxDynamicSharedMemorySize, SMEM_DYN);

    float *pA, *pValid, *pRatio, *pM2;
    float2* pPart;
    half_t *pxh, *phh, *pw1h, *pw2h, *pw3h;
    cudaGetSymbolAddress((void**)&pA, g_bufA);
    cudaGetSymbolAddress((void**)&pValid, g_valid);
    cudaGetSymbolAddress((void**)&pRatio, g_ratio);
    cudaGetSymbolAddress((void**)&pM2, g_m2);
    cudaGetSymbolAddress((void**)&pPart, g_part2);
    cudaGetSymbolAddress((void**)&pxh, g_xh);
    cudaGetSymbolAddress((void**)&phh, g_hh);
    cudaGetSymbolAddress((void**)&pw1h, g_w1h);
    cudaGetSymbolAddress((void**)&pw2h, g_w2h);
    cudaGetSymbolAddress((void**)&pw3h, g_w3h);

    const int nb = (NPTS + 255) / 256;
    valid_kernel<<<nb, 256>>>(mask);
    ratio_kernel<<<nb, 256>>>(mask, nbr, mout);
    convert_x<<<(int)(((size_t)NPTS * CH_IN + 255) / 256), 256>>>(x);
    prep_w<<<(W1E + W2E + W3E + 255) / 256, 256>>>(W1, W2, W3);

    // conv1: t1 = (x @ W1) * valid   [Kd=512]
    mma_gemm<<<dim3(1, NROWT), 256, SMEM_DYN>>>(pxh, CH_IN, nullptr,
        pw1h, CH_IN, pA, PP, NPTS, CH_IN, pValid, pPart, PP);
    stats_final<<<1, PP>>>(pPart, PP, NPTS, NROWT);
    ew_split<<<(NPTS * PP + 255) / 256, 256>>>(pA, 1);

    // conv2 gathered: Kd = 27*128 = 3456
    mma_gemm<<<dim3(1, NROWT), 256, SMEM_DYN>>>(phh, PP, nbr,
        pw2h, KNB * PP, pA, PP, NPTS, KNB * PP, pRatio, pPart, PP);
    stats_final<<<1, PP>>>(pPart, PP, NPTS, NROWT);
    ew_split<<<(NPTS * PP + 255) / 256, 256>>>(pA, 0);

    // conv3: out = (h2 @ W3) * m2   [N=512 via 4 column tiles, Kd=128]
    mma_gemm<<<dim3(4, NROWT), 256, SMEM_DYN>>>(phh, PP, nullptr,
        pw3h, PP, out, CH_IN, NPTS, PP, pM2, pPart, CH_IN);
    stats_final<<<1, CH_IN>>>(pPart, CH_IN, NPTS, NROWT);
    ew_final<<<(int)(((size_t)NPTS * CH_IN + 255) / 256), 256>>>(x, out);
}